// round 1
// baseline (speedup 1.0000x reference)
#include <cuda_runtime.h>
#include <cstdint>

#define Tn 168
#define Pn 16
#define Hn 24
#define Gn 96
#define Bn 8192
#define EPC 28               // batch elements per CTA
#define TPE 8                // threads per element
#define NTHREADS (EPC*TPE)   // 224
#define XSTRIDE 20           // padded x row (floats)
#define GSTRIDE 100          // padded gate row (floats)

// ---- packed f32x2 helpers (FFMA2 only reachable via PTX) ----
__device__ __forceinline__ unsigned long long pk2(float lo, float hi) {
    unsigned long long r;
    asm("mov.b64 %0, {%1, %2};" : "=l"(r) : "f"(lo), "f"(hi));
    return r;
}
__device__ __forceinline__ void fma2(unsigned long long& d, unsigned long long a, unsigned long long b) {
    asm("fma.rn.f32x2 %0, %1, %2, %0;" : "+l"(d) : "l"(a), "l"(b));
}
__device__ __forceinline__ void unpk2(unsigned long long v, float& lo, float& hi) {
    asm("mov.b64 {%0, %1}, %2;" : "=f"(lo), "=f"(hi) : "l"(v));
}

__device__ __forceinline__ float sigf(float x) {
    return __fdividef(1.0f, 1.0f + __expf(-x));
}
__device__ __forceinline__ float tanhfast(float x) {
    // tanh(x) = 1 - 2/(1+e^{2x}); exact limits at +-inf via __fdividef(.,inf)=0
    return 1.0f - __fdividef(2.0f, 1.0f + __expf(2.0f * x));
}

__global__ __launch_bounds__(NTHREADS, 2)
void lstm_fused_kernel(const float* __restrict__ x,
                       const float* __restrict__ Wih,   // [96,16]
                       const float* __restrict__ Whh,   // [96,24]
                       const float* __restrict__ bih,   // [96]
                       const float* __restrict__ bhh,   // [96]
                       const float* __restrict__ Wlin,  // [24,24]
                       const float* __restrict__ blin,  // [24]
                       float* __restrict__ out)         // [8192,24]
{
    __shared__ float sWih[Pn * Gn];     // [p][g]
    __shared__ float sWhh[Hn * Gn];     // [k][g]
    __shared__ float sB[Gn];            // bih+bhh
    __shared__ float sWlin[Hn * Hn];    // [j][m]
    __shared__ float sBlin[Hn];
    __shared__ float sX[2][EPC * XSTRIDE];
    __shared__ float sH[EPC * Hn];
    __shared__ float sG[EPC * GSTRIDE];

    const int tid = threadIdx.x;
    const int el  = tid / TPE;          // 0..27  local element
    const int l8  = tid % TPE;          // 0..7
    const int eg  = blockIdx.x * EPC + el;
    const bool live = (eg < Bn);
    const int g0 = l8 * 12;             // first owned gate index
    const int j0 = l8 * 3;              // first owned h index

    // ---- prologue: stage weights (transposed for packed access) ----
    for (int i = tid; i < Pn * Gn; i += NTHREADS) {
        int g = i >> 4, p = i & 15;
        sWih[p * Gn + g] = Wih[i];
    }
    for (int i = tid; i < Hn * Gn; i += NTHREADS) {
        int g = i / Hn, k = i - g * Hn;
        sWhh[k * Gn + g] = Whh[i];
    }
    for (int i = tid; i < Gn; i += NTHREADS) sB[i] = bih[i] + bhh[i];
    for (int i = tid; i < Hn * Hn; i += NTHREADS) {
        int m = i / Hn, j = i - m * Hn;
        sWlin[j * Hn + m] = Wlin[i];
    }
    for (int i = tid; i < Hn; i += NTHREADS) sBlin[i] = blin[i];
    for (int i = tid; i < EPC * Hn; i += NTHREADS) sH[i] = 0.0f;

    // x(t=0): each thread loads a float2 of its own element's row
    {
        float2 v = make_float2(0.0f, 0.0f);
        if (live) v = *reinterpret_cast<const float2*>(&x[(size_t)eg * (Tn * Pn) + l8 * 2]);
        sX[0][el * XSTRIDE + l8 * 2]     = v.x;
        sX[0][el * XSTRIDE + l8 * 2 + 1] = v.y;
    }
    __syncthreads();

    // per-thread packed bias (6 x f32x2)
    unsigned long long bias[6];
    {
        const float* bp = &sB[g0];
#pragma unroll
        for (int q = 0; q < 6; q++) bias[q] = pk2(bp[2 * q], bp[2 * q + 1]);
    }

    // weight views: 16B-aligned (g0*4 = 48B multiple of 16)
    const ulonglong2* wih2 = reinterpret_cast<const ulonglong2*>(&sWih[g0]); // row p -> [p*24 + s]
    const ulonglong2* whh2 = reinterpret_cast<const ulonglong2*>(&sWhh[g0]); // row k -> [k*24 + s]

    float c[3] = {0.0f, 0.0f, 0.0f};
    float hown[3] = {0.0f, 0.0f, 0.0f};

    for (int t = 0; t < Tn; t++) {
        const int buf = t & 1;

        // prefetch next-step x early (covers ~600cy DRAM latency under compute)
        float2 xpf = make_float2(0.0f, 0.0f);
        if (t + 1 < Tn && live)
            xpf = *reinterpret_cast<const float2*>(&x[(size_t)eg * (Tn * Pn) + (t + 1) * Pn + l8 * 2]);

        // load this element's x_t and h into registers (broadcast LDS.128)
        float xr[16];
        {
            const float4* xv = reinterpret_cast<const float4*>(&sX[buf][el * XSTRIDE]);
#pragma unroll
            for (int s = 0; s < 4; s++) {
                float4 v = xv[s];
                xr[4 * s] = v.x; xr[4 * s + 1] = v.y; xr[4 * s + 2] = v.z; xr[4 * s + 3] = v.w;
            }
        }
        float hr[24];
        {
            const float4* hv = reinterpret_cast<const float4*>(&sH[el * Hn]);
#pragma unroll
            for (int s = 0; s < 6; s++) {
                float4 v = hv[s];
                hr[4 * s] = v.x; hr[4 * s + 1] = v.y; hr[4 * s + 2] = v.z; hr[4 * s + 3] = v.w;
            }
        }

        // gate pre-activations: acc = bias + x.Wih + h.Whh   (12 gates = 6 f32x2)
        unsigned long long acc[6];
#pragma unroll
        for (int q = 0; q < 6; q++) acc[q] = bias[q];

#pragma unroll
        for (int p = 0; p < Pn; p++) {
            unsigned long long xs = pk2(xr[p], xr[p]);
#pragma unroll
            for (int s = 0; s < 3; s++) {
                ulonglong2 w = wih2[p * 24 + s];
                fma2(acc[2 * s],     xs, w.x);
                fma2(acc[2 * s + 1], xs, w.y);
            }
        }
#pragma unroll
        for (int k = 0; k < Hn; k++) {
            unsigned long long hs = pk2(hr[k], hr[k]);
#pragma unroll
            for (int s = 0; s < 3; s++) {
                ulonglong2 w = whh2[k * 24 + s];
                fma2(acc[2 * s],     hs, w.x);
                fma2(acc[2 * s + 1], hs, w.y);
            }
        }

        // publish gates
        {
            float4* gw = reinterpret_cast<float4*>(&sG[el * GSTRIDE + g0]);
#pragma unroll
            for (int s = 0; s < 3; s++) {
                float4 v;
                unpk2(acc[2 * s],     v.x, v.y);
                unpk2(acc[2 * s + 1], v.z, v.w);
                gw[s] = v;
            }
        }
        __syncthreads();   // gates visible; all sH/sX[buf] reads complete

        // elementwise on owned h-indices (c stays in registers)
        {
            const float* ge = &sG[el * GSTRIDE];
#pragma unroll
            for (int q = 0; q < 3; q++) {
                int j = j0 + q;
                float iv = sigf(ge[j]);
                float fv = sigf(ge[24 + j]);
                float gv = tanhfast(ge[48 + j]);
                float ov = sigf(ge[72 + j]);
                c[q] = fv * c[q] + iv * gv;
                float hval = ov * tanhfast(c[q]);
                hown[q] = hval;
                sH[el * Hn + j] = hval;
            }
        }
        // stage prefetched x into the other buffer
        if (t + 1 < Tn) {
            sX[(t + 1) & 1][el * XSTRIDE + l8 * 2]     = xpf.x;
            sX[(t + 1) & 1][el * XSTRIDE + l8 * 2 + 1] = xpf.y;
        }
        __syncthreads();   // h(t) and x(t+1) visible
    }

    // ---- epilogue: out = tanh(h_last) @ Wlin^T + blin ----
#pragma unroll
    for (int q = 0; q < 3; q++)
        sG[el * GSTRIDE + j0 + q] = tanhfast(hown[q]);
    __syncthreads();

    {
        const int m0 = l8 * 3;
        float a0 = sBlin[m0], a1 = sBlin[m0 + 1], a2 = sBlin[m0 + 2];
        const float* th = &sG[el * GSTRIDE];
#pragma unroll
        for (int j = 0; j < Hn; j++) {
            float tv = th[j];
            a0 += tv * sWlin[j * Hn + m0];
            a1 += tv * sWlin[j * Hn + m0 + 1];
            a2 += tv * sWlin[j * Hn + m0 + 2];
        }
        if (live) {
            out[(size_t)eg * Hn + m0]     = a0;
            out[(size_t)eg * Hn + m0 + 1] = a1;
            out[(size_t)eg * Hn + m0 + 2] = a2;
        }
    }
}

extern "C" void kernel_launch(void* const* d_in, const int* in_sizes, int n_in,
                              void* d_out, int out_size) {
    const float* x    = (const float*)d_in[0];
    const float* Wih  = (const float*)d_in[1];
    const float* Whh  = (const float*)d_in[2];
    const float* bih  = (const float*)d_in[3];
    const float* bhh  = (const float*)d_in[4];
    const float* Wlin = (const float*)d_in[5];
    const float* blin = (const float*)d_in[6];
    float* out = (float*)d_out;

    const int grid = (Bn + EPC - 1) / EPC;  // 293
    lstm_fused_kernel<<<grid, NTHREADS>>>(x, Wih, Whh, bih, bhh, Wlin, blin, out);
}

// round 2
// speedup vs baseline: 1.6698x; 1.6698x over previous
#include <cuda_runtime.h>
#include <cstdint>

#define Tn 168
#define Pn 16
#define Hn 24
#define Gn 96
#define Bn 8192
#define TPE 8                 // threads per element-group
#define GRP 28                // groups per CTA
#define En 2                  // elements per thread
#define EPC (GRP*En)          // 56 elements per CTA
#define NTHREADS (GRP*TPE)    // 224
#define XSTRIDE 20            // padded x row (floats)  -> banks 0,8,16,24 pattern, conflict-free
#define HSTRIDE 28            // padded h row (floats)  -> conflict-free float4 loads

// ---- packed f32x2 helpers ----
__device__ __forceinline__ unsigned long long pk2(float lo, float hi) {
    unsigned long long r;
    asm("mov.b64 %0, {%1, %2};" : "=l"(r) : "f"(lo), "f"(hi));
    return r;
}
__device__ __forceinline__ void fma2(unsigned long long& d, unsigned long long a, unsigned long long b) {
    asm("fma.rn.f32x2 %0, %1, %2, %0;" : "+l"(d) : "l"(a), "l"(b));
}
__device__ __forceinline__ void unpk2(unsigned long long v, float& lo, float& hi) {
    asm("mov.b64 {%0, %1}, %2;" : "=f"(lo), "=f"(hi) : "l"(v));
}

__device__ __forceinline__ float sigf(float x) {
    return __fdividef(1.0f, 1.0f + __expf(-x));
}
__device__ __forceinline__ float tanhfast(float x) {
    return 1.0f - __fdividef(2.0f, 1.0f + __expf(2.0f * x));
}

__global__ __launch_bounds__(NTHREADS, 1)
void lstm_fused_kernel(const float* __restrict__ x,
                       const float* __restrict__ Wih,   // [96,16]
                       const float* __restrict__ Whh,   // [96,24]
                       const float* __restrict__ bih,   // [96]
                       const float* __restrict__ bhh,   // [96]
                       const float* __restrict__ Wlin,  // [24,24]
                       const float* __restrict__ blin,  // [24]
                       float* __restrict__ out)         // [8192,24]
{
    // Weight layout: per-thread-owned 12 gate columns contiguous.
    // Thread l8 owns gates {i_j, f_j, g_j, o_j : j in [3*l8, 3*l8+3)}
    // stored at column l8*12 + (type*3 + j%3).
    __shared__ float sWih[Pn * Gn];     // [p][owner-major 96]
    __shared__ float sWhh[Hn * Gn];     // [k][owner-major 96]
    __shared__ float sWlin[Hn * Hn];    // [j][m]
    __shared__ float sBlin[Hn];
    __shared__ float sX[2][EPC * XSTRIDE];
    __shared__ float sH[2][EPC * HSTRIDE];

    const int tid = threadIdx.x;
    const int grp = tid / TPE;          // 0..27
    const int l8  = tid % TPE;          // 0..7
    const int el0 = grp * En;           // local element of e=0
    const int eg0 = blockIdx.x * EPC + el0;
    const int j0  = l8 * 3;

    // ---- prologue: stage + reorder weights ----
    for (int i = tid; i < Pn * Gn; i += NTHREADS) {
        int g = i >> 4, p = i & 15;
        int tt = g / Hn, j = g - tt * Hn;
        int own = (j / 3) * 12 + tt * 3 + (j % 3);
        sWih[p * Gn + own] = Wih[i];
    }
    for (int i = tid; i < Hn * Gn; i += NTHREADS) {
        int g = i / Hn, k = i - g * Hn;
        int tt = g / Hn, j = g - tt * Hn;
        int own = (j / 3) * 12 + tt * 3 + (j % 3);
        sWhh[k * Gn + own] = Whh[i];
    }
    for (int i = tid; i < Hn * Hn; i += NTHREADS) {
        int m = i / Hn, j = i - m * Hn;
        sWlin[j * Hn + m] = Wlin[i];
    }
    for (int i = tid; i < Hn; i += NTHREADS) sBlin[i] = blin[i];
    for (int i = tid; i < EPC * HSTRIDE; i += NTHREADS) { sH[0][i] = 0.0f; sH[1][i] = 0.0f; }

    // per-thread packed bias for owned 12 gates
    unsigned long long bias[6];
    {
        float bv[12];
#pragma unroll
        for (int q = 0; q < 12; q++) {
            int tt = q / 3;
            int g = tt * Hn + j0 + (q - tt * 3);
            bv[q] = bih[g] + bhh[g];
        }
#pragma unroll
        for (int s = 0; s < 6; s++) bias[s] = pk2(bv[2 * s], bv[2 * s + 1]);
    }

    // x(t=0): each thread stages its float2 for each of its E elements
#pragma unroll
    for (int e = 0; e < En; e++) {
        float2 v = make_float2(0.0f, 0.0f);
        int eg = eg0 + e;
        if (eg < Bn) v = *reinterpret_cast<const float2*>(&x[(size_t)eg * (Tn * Pn) + l8 * 2]);
        sX[0][(el0 + e) * XSTRIDE + l8 * 2]     = v.x;
        sX[0][(el0 + e) * XSTRIDE + l8 * 2 + 1] = v.y;
    }
    __syncthreads();

    // 16B-aligned per-thread weight views (l8*12 floats = 48B, multiple of 16)
    const ulonglong2* wih2 = reinterpret_cast<const ulonglong2*>(&sWih[l8 * 12]); // + p*24
    const ulonglong2* whh2 = reinterpret_cast<const ulonglong2*>(&sWhh[l8 * 12]); // + k*24

    float c[En][3];
    float hown[En][3];
#pragma unroll
    for (int e = 0; e < En; e++)
#pragma unroll
        for (int q = 0; q < 3; q++) { c[e][q] = 0.0f; hown[e][q] = 0.0f; }

    for (int t = 0; t < Tn; t++) {
        const int buf = t & 1;
        const int nbuf = buf ^ 1;

        // prefetch x(t+1) (global, L1/L2 resident after first touch of line)
        float2 xpf[En];
#pragma unroll
        for (int e = 0; e < En; e++) {
            xpf[e] = make_float2(0.0f, 0.0f);
            int eg = eg0 + e;
            if (t + 1 < Tn && eg < Bn)
                xpf[e] = *reinterpret_cast<const float2*>(
                    &x[(size_t)eg * (Tn * Pn) + (t + 1) * Pn + l8 * 2]);
        }

        // h(t-1) into registers (broadcast float4 LDS, conflict-free via HSTRIDE=28)
        float hr[En][Hn];
#pragma unroll
        for (int e = 0; e < En; e++) {
            const float4* hv = reinterpret_cast<const float4*>(&sH[buf][(el0 + e) * HSTRIDE]);
#pragma unroll
            for (int s = 0; s < 6; s++) {
                float4 v = hv[s];
                hr[e][4 * s] = v.x; hr[e][4 * s + 1] = v.y;
                hr[e][4 * s + 2] = v.z; hr[e][4 * s + 3] = v.w;
            }
        }

        // gate pre-activations for E elements (weights loaded ONCE, used E times)
        unsigned long long acc[En][6];
#pragma unroll
        for (int e = 0; e < En; e++)
#pragma unroll
            for (int s = 0; s < 6; s++) acc[e][s] = bias[s];

#pragma unroll
        for (int p = 0; p < Pn; p++) {
            ulonglong2 w0 = wih2[p * 24];
            ulonglong2 w1 = wih2[p * 24 + 1];
            ulonglong2 w2 = wih2[p * 24 + 2];
#pragma unroll
            for (int e = 0; e < En; e++) {
                float xv = sX[buf][(el0 + e) * XSTRIDE + p];
                unsigned long long xs = pk2(xv, xv);
                fma2(acc[e][0], xs, w0.x);
                fma2(acc[e][1], xs, w0.y);
                fma2(acc[e][2], xs, w1.x);
                fma2(acc[e][3], xs, w1.y);
                fma2(acc[e][4], xs, w2.x);
                fma2(acc[e][5], xs, w2.y);
            }
        }
#pragma unroll
        for (int k = 0; k < Hn; k++) {
            ulonglong2 w0 = whh2[k * 24];
            ulonglong2 w1 = whh2[k * 24 + 1];
            ulonglong2 w2 = whh2[k * 24 + 2];
#pragma unroll
            for (int e = 0; e < En; e++) {
                unsigned long long hs = pk2(hr[e][k], hr[e][k]);
                fma2(acc[e][0], hs, w0.x);
                fma2(acc[e][1], hs, w0.y);
                fma2(acc[e][2], hs, w1.x);
                fma2(acc[e][3], hs, w1.y);
                fma2(acc[e][4], hs, w2.x);
                fma2(acc[e][5], hs, w2.y);
            }
        }

        // thread-local elementwise (gates i/f/g/o for owned j all live here)
#pragma unroll
        for (int e = 0; e < En; e++) {
            float v[12];
#pragma unroll
            for (int s = 0; s < 6; s++) unpk2(acc[e][s], v[2 * s], v[2 * s + 1]);
#pragma unroll
            for (int q = 0; q < 3; q++) {
                float iv = sigf(v[q]);
                float fv = sigf(v[3 + q]);
                float gv = tanhfast(v[6 + q]);
                float ov = sigf(v[9 + q]);
                c[e][q] = fv * c[e][q] + iv * gv;
                float hval = ov * tanhfast(c[e][q]);
                hown[e][q] = hval;
                sH[nbuf][(el0 + e) * HSTRIDE + j0 + q] = hval;
            }
        }

        // stage prefetched x
        if (t + 1 < Tn) {
#pragma unroll
            for (int e = 0; e < En; e++) {
                sX[nbuf][(el0 + e) * XSTRIDE + l8 * 2]     = xpf[e].x;
                sX[nbuf][(el0 + e) * XSTRIDE + l8 * 2 + 1] = xpf[e].y;
            }
        }
        __syncthreads();   // single barrier: h(t), x(t+1) visible
    }

    // ---- epilogue: out = tanh(h_last) @ Wlin^T + blin ----
    // reuse sH[1] (no longer read) for tanh(h)
#pragma unroll
    for (int e = 0; e < En; e++)
#pragma unroll
        for (int q = 0; q < 3; q++)
            sH[1][(el0 + e) * HSTRIDE + j0 + q] = tanhfast(hown[e][q]);
    __syncthreads();

    {
        const int m0 = l8 * 3;
#pragma unroll
        for (int e = 0; e < En; e++) {
            int eg = eg0 + e;
            float a0 = sBlin[m0], a1 = sBlin[m0 + 1], a2 = sBlin[m0 + 2];
            const float* th = &sH[1][(el0 + e) * HSTRIDE];
#pragma unroll
            for (int j = 0; j < Hn; j++) {
                float tv = th[j];
                a0 += tv * sWlin[j * Hn + m0];
                a1 += tv * sWlin[j * Hn + m0 + 1];
                a2 += tv * sWlin[j * Hn + m0 + 2];
            }
            if (eg < Bn) {
                out[(size_t)eg * Hn + m0]     = a0;
                out[(size_t)eg * Hn + m0 + 1] = a1;
                out[(size_t)eg * Hn + m0 + 2] = a2;
            }
        }
    }
}

extern "C" void kernel_launch(void* const* d_in, const int* in_sizes, int n_in,
                              void* d_out, int out_size) {
    const float* x    = (const float*)d_in[0];
    const float* Wih  = (const float*)d_in[1];
    const float* Whh  = (const float*)d_in[2];
    const float* bih  = (const float*)d_in[3];
    const float* bhh  = (const float*)d_in[4];
    const float* Wlin = (const float*)d_in[5];
    const float* blin = (const float*)d_in[6];
    float* out = (float*)d_out;

    const int grid = (Bn + EPC - 1) / EPC;  // 147 -> exactly 1 CTA per SM
    lstm_fused_kernel<<<grid, NTHREADS>>>(x, Wih, Whh, bih, bhh, Wlin, blin, out);
}